// round 9
// baseline (speedup 1.0000x reference)
#include <cuda_runtime.h>
#include <cuda_bf16.h>

#define T_STEPS 256
#define BATCH   128
#define DIM_IN  512
#define HID     512
#define NQ      8
#define QDIM    256   // 2^8

// ---------------- scratch (no allocations allowed) ----------------
__device__ float4 g_xdot[T_STEPS * BATCH];   // per (t,b): raw dots for f,i,g,o
__device__ float  g_H[T_STEPS * BATCH];      // scalar hidden state per (t,b)
__device__ float  g_Cfin[BATCH];             // final cell scalar per b
// per gate: [0]=wsum  [1]=b0-phi  [2]=alpha/2  [3]=R/2  [4]=alpha  [5]=R
__device__ float  g_par[4][6];

__device__ __forceinline__ float2 cmul(float2 a, float2 b) {
    return make_float2(a.x * b.x - a.y * b.y, a.x * b.y + a.y * b.x);
}
__device__ __forceinline__ float2 cadd(float2 a, float2 b) {
    return make_float2(a.x + b.x, a.y + b.y);
}
__device__ __forceinline__ float htanh(float x) {
    float y;
    asm("tanh.approx.f32 %0, %1;" : "=f"(y) : "f"(x));
    return y;
}
__device__ __forceinline__ float dot4(float4 w, float4 x) {
    return w.x * x.x + w.y * x.y + w.z * x.z + w.w * x.w;
}

// ---------------- circuit: simulate one variational circuit ----------------
// Statevector-simulates columns 0 and 128 of the 2-layer circuit, reduces to
// expval(theta) = alpha + R*cos(theta - phi), plus wsum and b0-phi.
__device__ void circuit_block(int g, const float* __restrict__ P,
                              const float* __restrict__ W, const float* __restrict__ bv)
{
    __shared__ float2 a0[QDIM], a1[QDIM];
    __shared__ float  r0[QDIM], r1[QDIM], r2[QDIM];
    int d = threadIdx.x;

    a0[d] = make_float2(d == 0 ? 1.f : 0.f, 0.f);
    a1[d] = make_float2(d == QDIM / 2 ? 1.f : 0.f, 0.f);

    for (int l = 0; l < 2; l++) {
        for (int w = 0; w < NQ; w++) {
            const float* p = P + (l * NQ + w) * 3;
            float phi = p[0], th = p[1], om = p[2];
            float c, s;  __sincosf(0.5f * th, &s, &c);
            float cap, sap; __sincosf(0.5f * (phi + om), &sap, &cap);
            float cbm, sbm; __sincosf(0.5f * (phi - om), &sbm, &cbm);
            float2 m00 = make_float2(cap * c, -sap * c);     // ep*c
            float2 m01 = make_float2(-cbm * s, -sbm * s);    // -em*s
            float2 m10 = make_float2(cbm * s, -sbm * s);     // conj(em)*s
            float2 m11 = make_float2(cap * c, sap * c);      // conj(ep)*c

            int p7 = 7 - w;
            int mask = 1 << p7;
            int bit = (d >> p7) & 1;
            __syncthreads();
            float2 me0 = a0[d], pa0 = a0[d ^ mask];
            float2 me1 = a1[d], pa1 = a1[d ^ mask];
            __syncthreads();
            float2 n0, n1;
            if (!bit) {
                n0 = cadd(cmul(m00, me0), cmul(m01, pa0));
                n1 = cadd(cmul(m00, me1), cmul(m01, pa1));
            } else {
                n0 = cadd(cmul(m10, pa0), cmul(m11, me0));
                n1 = cadd(cmul(m10, pa1), cmul(m11, me1));
            }
            a0[d] = n0; a1[d] = n1;
        }
        for (int w = 0; w < NQ - 1; w++) {
            int pc = 7 - w, pt = 6 - w;
            __syncthreads();
            int src = ((d >> pc) & 1) ? (d ^ (1 << pt)) : d;
            float2 v0 = a0[src], v1 = a1[src];
            __syncthreads();
            a0[d] = v0; a1[d] = v1;
        }
    }
    __syncthreads();

    float z = (d < QDIM / 2) ? 1.f : -1.f;
    float2 c0 = a0[d], c1 = a1[d];
    r0[d] = z * (c0.x * c0.x + c0.y * c0.y);
    r1[d] = z * (c1.x * c1.x + c1.y * c1.y);
    r2[d] = z * (c0.y * c1.x - c0.x * c1.y);
    __syncthreads();
    for (int off = QDIM / 2; off; off >>= 1) {
        if (d < off) { r0[d] += r0[d + off]; r1[d] += r1[d + off]; r2[d] += r2[d + off]; }
        __syncthreads();
    }
    float S00 = r0[0], S11 = r1[0], S01 = r2[0];
    __syncthreads();

    r0[d] = W[512 + d] + W[512 + QDIM + d];
    __syncthreads();
    for (int off = QDIM / 2; off; off >>= 1) {
        if (d < off) r0[d] += r0[d + off];
        __syncthreads();
    }
    if (d == 0) {
        float alpha = 0.5f * (S00 + S11);
        float beta  = 0.5f * (S00 - S11);
        float gamma = -S01;
        float R   = sqrtf(beta * beta + gamma * gamma);
        float phi = atan2f(gamma, beta);
        g_par[g][0] = r0[0];          // wsum
        g_par[g][1] = bv[0] - phi;    // theta offset (added in scan)
        g_par[g][2] = 0.5f * alpha;
        g_par[g][3] = 0.5f * R;
        g_par[g][4] = alpha;
        g_par[g][5] = R;
    }
}

// ---------------- prep: circuit (blocks 0-3) + weight-stationary xdot ----------------
// Each warp holds ALL 4 gates' weights in registers (loaded once) and streams
// 8 contiguous rows of X with a 1-row-ahead prefetch. L1 traffic = X only.
__global__ void __launch_bounds__(256, 2) prep_kernel(
    const float* __restrict__ X,
    const float* __restrict__ Wf, const float* __restrict__ Wi,
    const float* __restrict__ Wg, const float* __restrict__ Wo,
    const float* __restrict__ bfv, const float* __restrict__ biv,
    const float* __restrict__ bgv, const float* __restrict__ bov,
    const float* __restrict__ Pf, const float* __restrict__ Pi,
    const float* __restrict__ Pg, const float* __restrict__ Po)
{
    if (blockIdx.x < 4) {
        int g = blockIdx.x;
        const float* P  = (g == 0) ? Pf : (g == 1) ? Pi : (g == 2) ? Pg : Po;
        const float* W  = (g == 0) ? Wf : (g == 1) ? Wi : (g == 2) ? Wg : Wo;
        const float* bv = (g == 0) ? bfv : (g == 1) ? biv : (g == 2) ? bgv : bov;
        circuit_block(g, P, W, bv);
        return;
    }

    int warp  = threadIdx.x >> 5;
    int lane  = threadIdx.x & 31;
    int gwarp = (blockIdx.x - 4) * 8 + warp;   // 0..4095
    int row0  = gwarp * 8;                     // 8 rows per warp

    // weights: 4 gates x 4 float4 per lane, resident for the whole kernel
    const float4* wf4 = (const float4*)Wf;
    const float4* wi4 = (const float4*)Wi;
    const float4* wg4 = (const float4*)Wg;
    const float4* wo4 = (const float4*)Wo;
    float4 wf0 = __ldg(wf4 + lane), wf1 = __ldg(wf4 + lane + 32),
           wf2 = __ldg(wf4 + lane + 64), wf3 = __ldg(wf4 + lane + 96);
    float4 wi0 = __ldg(wi4 + lane), wi1 = __ldg(wi4 + lane + 32),
           wi2 = __ldg(wi4 + lane + 64), wi3 = __ldg(wi4 + lane + 96);
    float4 wg0 = __ldg(wg4 + lane), wg1 = __ldg(wg4 + lane + 32),
           wg2 = __ldg(wg4 + lane + 64), wg3 = __ldg(wg4 + lane + 96);
    float4 wo0 = __ldg(wo4 + lane), wo1 = __ldg(wo4 + lane + 32),
           wo2 = __ldg(wo4 + lane + 64), wo3 = __ldg(wo4 + lane + 96);

    const float4* xr = (const float4*)(X + (size_t)row0 * DIM_IN);

    // prefetch row 0
    float4 x0 = xr[lane], x1 = xr[lane + 32], x2 = xr[lane + 64], x3 = xr[lane + 96];

#pragma unroll 1
    for (int r = 0; r < 8; r++) {
        float4 c0 = x0, c1 = x1, c2 = x2, c3 = x3;
        if (r < 7) {
            const float4* xn = xr + (r + 1) * (DIM_IN / 4);
            x0 = xn[lane]; x1 = xn[lane + 32]; x2 = xn[lane + 64]; x3 = xn[lane + 96];
        }

        float sf = dot4(wf0, c0) + dot4(wf1, c1) + dot4(wf2, c2) + dot4(wf3, c3);
        float si = dot4(wi0, c0) + dot4(wi1, c1) + dot4(wi2, c2) + dot4(wi3, c3);
        float sg = dot4(wg0, c0) + dot4(wg1, c1) + dot4(wg2, c2) + dot4(wg3, c3);
        float so = dot4(wo0, c0) + dot4(wo1, c1) + dot4(wo2, c2) + dot4(wo3, c3);

#pragma unroll
        for (int o = 16; o; o >>= 1) {
            sf += __shfl_xor_sync(0xffffffffu, sf, o);
            si += __shfl_xor_sync(0xffffffffu, si, o);
            sg += __shfl_xor_sync(0xffffffffu, sg, o);
            so += __shfl_xor_sync(0xffffffffu, so, o);
        }
        if (lane == 0) g_xdot[row0 + r] = make_float4(sf, si, sg, so);
    }
}

// ---------------- scan: 128 scalar recurrences, 256 steps ----------------
// theta_g = (xd_g + off_g) + H*ws_g ; gate = act(alpha_g + R_g*cos(theta_g)).
// Sigmoid tanh-args are in [-0.55,0.55] (expval in [-1,1]) -> 7th-order odd
// Taylor on the FMA pipe; gv and tanh(C) stay on HW tanh.
__device__ __forceinline__ float ptanh_half(float x) {   // |x| <= ~0.55
    float t = x * x;
    float p = fmaf(t, -17.f / 315.f, 2.f / 15.f);
    p = fmaf(t, p, -1.f / 3.f);
    p = fmaf(t, p, 1.f);
    return x * p;
}

__global__ void scan_kernel()
{
    int b = threadIdx.x;

    float ws_f = g_par[0][0], A2_f = g_par[0][2], R2_f = g_par[0][3];
    float ws_i = g_par[1][0], A2_i = g_par[1][2], R2_i = g_par[1][3];
    float ws_g = g_par[2][0], A_g  = g_par[2][4], R_g  = g_par[2][5];
    float ws_o = g_par[3][0], A2_o = g_par[3][2], R2_o = g_par[3][3];
    float off_f = g_par[0][1], off_i = g_par[1][1], off_g = g_par[2][1], off_o = g_par[3][1];

    float H = 0.f, C = 0.f;

    const float4* X = g_xdot;
#define LOADADJ(t) \
    ({ float4 v_ = X[(t) * BATCH + b]; \
       v_.x += off_f; v_.y += off_i; v_.z += off_g; v_.w += off_o; v_; })

    float4 q[8];
#pragma unroll
    for (int j = 0; j < 8; j++) q[j] = LOADADJ(j);

#define STEP(xd, t)                                                   \
    {                                                                 \
        float cf = __cosf(fmaf(H, ws_f, (xd).x));                     \
        float ci = __cosf(fmaf(H, ws_i, (xd).y));                     \
        float cg = __cosf(fmaf(H, ws_g, (xd).z));                     \
        float co = __cosf(fmaf(H, ws_o, (xd).w));                     \
        float fv = fmaf(ptanh_half(fmaf(R2_f, cf, A2_f)), 0.5f, 0.5f);\
        float iv = fmaf(ptanh_half(fmaf(R2_i, ci, A2_i)), 0.5f, 0.5f);\
        float gv = htanh(fmaf(R_g, cg, A_g));                         \
        float ov = fmaf(ptanh_half(fmaf(R2_o, co, A2_o)), 0.5f, 0.5f);\
        C = fmaf(fv, C, iv * gv);                                     \
        H = ov * htanh(C);                                            \
        g_H[(t) * BATCH + b] = H;                                     \
    }

#pragma unroll 1
    for (int t = 0; t < T_STEPS; t += 8) {
#pragma unroll
        for (int j = 0; j < 8; j++) {
            float4 cur = q[j];
            if (t + 8 + j < T_STEPS) q[j] = LOADADJ(t + 8 + j);
            STEP(cur, t + j);
        }
    }
#undef STEP
#undef LOADADJ
    g_Cfin[b] = C;
}

// ---------------- bcast: broadcast scalars into the full output ----------------
// Each block covers 512 consecutive float4s: 2 fully-coalesced stores/thread.
// d_out layout: outputs (T,B,512) ++ hx (B,512) ++ cx (B,512).
__device__ __forceinline__ float bcast_val(unsigned i, unsigned OUT4, unsigned HB4)
{
    if (i < OUT4)           return g_H[i >> 7];
    if (i < OUT4 + HB4)     return g_H[(T_STEPS - 1) * BATCH + ((i - OUT4) >> 7)];
    return g_Cfin[(i - OUT4 - HB4) >> 7];
}

__global__ void bcast_kernel(float4* __restrict__ out)
{
    const unsigned OUT4 = (unsigned)T_STEPS * BATCH * (HID / 4); // 4,194,304
    const unsigned HB4  = (unsigned)BATCH * (HID / 4);           // 16,384
    unsigned i0 = blockIdx.x * 512u + threadIdx.x;               // float4 index
    unsigned i1 = i0 + 256u;

    float v0 = bcast_val(i0, OUT4, HB4);
    float v1 = bcast_val(i1, OUT4, HB4);
    __stcs(out + i0, make_float4(v0, v0, v0, v0));
    __stcs(out + i1, make_float4(v1, v1, v1, v1));
}

// ---------------- launch ----------------
extern "C" void kernel_launch(void* const* d_in, const int* in_sizes, int n_in,
                              void* d_out, int out_size)
{
    const float* X  = (const float*)d_in[0];
    const float* Wf = (const float*)d_in[1];
    const float* bf = (const float*)d_in[2];
    const float* Pf = (const float*)d_in[3];
    const float* Wi = (const float*)d_in[4];
    const float* bi = (const float*)d_in[5];
    const float* Pi = (const float*)d_in[6];
    const float* Wg = (const float*)d_in[7];
    const float* bg = (const float*)d_in[8];
    const float* Pg = (const float*)d_in[9];
    const float* Wo = (const float*)d_in[10];
    const float* bo = (const float*)d_in[11];
    const float* Po = (const float*)d_in[12];

    // blocks 0-3: circuits; blocks 4..515: xdot (4096 warps x 8 rows = 32768 rows)
    prep_kernel<<<4 + 512, 256>>>(
        X, Wf, Wi, Wg, Wo, bf, bi, bg, bo, Pf, Pi, Pg, Po);

    scan_kernel<<<1, BATCH>>>();

    // 4,227,072 float4 / 512 per block = 8256 blocks
    bcast_kernel<<<8256, 256>>>((float4*)d_out);
}

// round 10
// speedup vs baseline: 1.1328x; 1.1328x over previous
#include <cuda_runtime.h>
#include <cuda_bf16.h>

#define T_STEPS 256
#define BATCH   128
#define DIM_IN  512
#define HID     512
#define NQ      8
#define QDIM    256   // 2^8

// ---------------- scratch (no allocations allowed) ----------------
__device__ float4 g_xdot[T_STEPS * BATCH];   // per (t,b): raw dots for f,i,g,o
// per gate: [0]=wsum  [1]=b0-phi  [2]=alpha/2  [3]=R/2  [4]=alpha  [5]=R
__device__ float  g_par[4][6];

__device__ __forceinline__ float2 cmul(float2 a, float2 b) {
    return make_float2(a.x * b.x - a.y * b.y, a.x * b.y + a.y * b.x);
}
__device__ __forceinline__ float2 cadd(float2 a, float2 b) {
    return make_float2(a.x + b.x, a.y + b.y);
}
__device__ __forceinline__ float htanh(float x) {
    float y;
    asm("tanh.approx.f32 %0, %1;" : "=f"(y) : "f"(x));
    return y;
}
__device__ __forceinline__ float dot4(float4 w, float4 x) {
    return w.x * x.x + w.y * x.y + w.z * x.z + w.w * x.w;
}

// ---------------- circuit: simulate one variational circuit ----------------
// Statevector-simulates columns 0 and 128 of the 2-layer circuit, reduces to
// expval(theta) = alpha + R*cos(theta - phi), plus wsum and b0-phi.
__device__ void circuit_block(int g, const float* __restrict__ P,
                              const float* __restrict__ W, const float* __restrict__ bv)
{
    __shared__ float2 a0[QDIM], a1[QDIM];
    __shared__ float  r0[QDIM], r1[QDIM], r2[QDIM];
    int d = threadIdx.x;

    a0[d] = make_float2(d == 0 ? 1.f : 0.f, 0.f);
    a1[d] = make_float2(d == QDIM / 2 ? 1.f : 0.f, 0.f);

    for (int l = 0; l < 2; l++) {
        for (int w = 0; w < NQ; w++) {
            const float* p = P + (l * NQ + w) * 3;
            float phi = p[0], th = p[1], om = p[2];
            float c, s;  __sincosf(0.5f * th, &s, &c);
            float cap, sap; __sincosf(0.5f * (phi + om), &sap, &cap);
            float cbm, sbm; __sincosf(0.5f * (phi - om), &sbm, &cbm);
            float2 m00 = make_float2(cap * c, -sap * c);     // ep*c
            float2 m01 = make_float2(-cbm * s, -sbm * s);    // -em*s
            float2 m10 = make_float2(cbm * s, -sbm * s);     // conj(em)*s
            float2 m11 = make_float2(cap * c, sap * c);      // conj(ep)*c

            int p7 = 7 - w;
            int mask = 1 << p7;
            int bit = (d >> p7) & 1;
            __syncthreads();
            float2 me0 = a0[d], pa0 = a0[d ^ mask];
            float2 me1 = a1[d], pa1 = a1[d ^ mask];
            __syncthreads();
            float2 n0, n1;
            if (!bit) {
                n0 = cadd(cmul(m00, me0), cmul(m01, pa0));
                n1 = cadd(cmul(m00, me1), cmul(m01, pa1));
            } else {
                n0 = cadd(cmul(m10, pa0), cmul(m11, me0));
                n1 = cadd(cmul(m10, pa1), cmul(m11, me1));
            }
            a0[d] = n0; a1[d] = n1;
        }
        for (int w = 0; w < NQ - 1; w++) {
            int pc = 7 - w, pt = 6 - w;
            __syncthreads();
            int src = ((d >> pc) & 1) ? (d ^ (1 << pt)) : d;
            float2 v0 = a0[src], v1 = a1[src];
            __syncthreads();
            a0[d] = v0; a1[d] = v1;
        }
    }
    __syncthreads();

    float z = (d < QDIM / 2) ? 1.f : -1.f;
    float2 c0 = a0[d], c1 = a1[d];
    r0[d] = z * (c0.x * c0.x + c0.y * c0.y);
    r1[d] = z * (c1.x * c1.x + c1.y * c1.y);
    r2[d] = z * (c0.y * c1.x - c0.x * c1.y);
    __syncthreads();
    for (int off = QDIM / 2; off; off >>= 1) {
        if (d < off) { r0[d] += r0[d + off]; r1[d] += r1[d + off]; r2[d] += r2[d + off]; }
        __syncthreads();
    }
    float S00 = r0[0], S11 = r1[0], S01 = r2[0];
    __syncthreads();

    r0[d] = W[512 + d] + W[512 + QDIM + d];
    __syncthreads();
    for (int off = QDIM / 2; off; off >>= 1) {
        if (d < off) r0[d] += r0[d + off];
        __syncthreads();
    }
    if (d == 0) {
        float alpha = 0.5f * (S00 + S11);
        float beta  = 0.5f * (S00 - S11);
        float gamma = -S01;
        float R   = sqrtf(beta * beta + gamma * gamma);
        float phi = atan2f(gamma, beta);
        g_par[g][0] = r0[0];          // wsum
        g_par[g][1] = bv[0] - phi;    // theta offset (added in scan)
        g_par[g][2] = 0.5f * alpha;
        g_par[g][3] = 0.5f * R;
        g_par[g][4] = alpha;
        g_par[g][5] = R;
    }
}

// ---------------- prep: circuit (blocks 0-3) + xdot, 2 rows per warp (R8 form) ----------------
__global__ void __launch_bounds__(256, 4) prep_kernel(
    const float* __restrict__ X,
    const float* __restrict__ Wf, const float* __restrict__ Wi,
    const float* __restrict__ Wg, const float* __restrict__ Wo,
    const float* __restrict__ bfv, const float* __restrict__ biv,
    const float* __restrict__ bgv, const float* __restrict__ bov,
    const float* __restrict__ Pf, const float* __restrict__ Pi,
    const float* __restrict__ Pg, const float* __restrict__ Po)
{
    if (blockIdx.x < 4) {
        int g = blockIdx.x;
        const float* P  = (g == 0) ? Pf : (g == 1) ? Pi : (g == 2) ? Pg : Po;
        const float* W  = (g == 0) ? Wf : (g == 1) ? Wi : (g == 2) ? Wg : Wo;
        const float* bv = (g == 0) ? bfv : (g == 1) ? biv : (g == 2) ? bgv : bov;
        circuit_block(g, P, W, bv);
        return;
    }

    int j    = blockIdx.x - 4;           // 0..2047 ; 16 rows per block
    int warp = threadIdx.x >> 5;
    int lane = threadIdx.x & 31;
    int rA   = j * 16 + warp * 2;        // rows rA, rA+1

    const float4* xa = (const float4*)(X + (size_t)rA * DIM_IN);
    const float4* xb = xa + (DIM_IN / 4);

    // front-batch all 8 X loads (MLP=8)
    float4 A0 = xa[lane], A1 = xa[lane + 32], A2 = xa[lane + 64], A3 = xa[lane + 96];
    float4 B0 = xb[lane], B1 = xb[lane + 32], B2 = xb[lane + 64], B3 = xb[lane + 96];

    float fA, fB, iA, iB, gA, gB, oA, oB;

#define GDOT(Wp, dA, dB)                                                          \
    {                                                                             \
        const float4* w4 = (const float4*)(Wp);                                   \
        float4 w0 = __ldg(w4 + lane),      w1 = __ldg(w4 + lane + 32),            \
               w2 = __ldg(w4 + lane + 64), w3 = __ldg(w4 + lane + 96);            \
        dA = dot4(w0, A0) + dot4(w1, A1) + dot4(w2, A2) + dot4(w3, A3);           \
        dB = dot4(w0, B0) + dot4(w1, B1) + dot4(w2, B2) + dot4(w3, B3);           \
    }
    GDOT(Wf, fA, fB)
    GDOT(Wi, iA, iB)
    GDOT(Wg, gA, gB)
    GDOT(Wo, oA, oB)
#undef GDOT

#pragma unroll
    for (int o = 16; o; o >>= 1) {
        fA += __shfl_xor_sync(0xffffffffu, fA, o);
        fB += __shfl_xor_sync(0xffffffffu, fB, o);
        iA += __shfl_xor_sync(0xffffffffu, iA, o);
        iB += __shfl_xor_sync(0xffffffffu, iB, o);
        gA += __shfl_xor_sync(0xffffffffu, gA, o);
        gB += __shfl_xor_sync(0xffffffffu, gB, o);
        oA += __shfl_xor_sync(0xffffffffu, oA, o);
        oB += __shfl_xor_sync(0xffffffffu, oB, o);
    }
    if (lane == 0) {
        g_xdot[rA]     = make_float4(fA, iA, gA, oA);
        g_xdot[rA + 1] = make_float4(fB, iB, gB, oB);
    }
}

// ---------------- scanout: fused scan + output write ----------------
// One block per batch element. Thread 0 runs the scalar recurrence; every
// 8-step chunk it stages H into double-buffered smem, and threads 32..255
// stream the previous chunk's 512-wide output rows to d_out concurrently.
// Only block-local __syncthreads — no cross-block sync.
__device__ __forceinline__ float ptanh_half(float x) {   // |x| <= ~0.55
    float t = x * x;
    float p = fmaf(t, -17.f / 315.f, 2.f / 15.f);
    p = fmaf(t, p, -1.f / 3.f);
    p = fmaf(t, p, 1.f);
    return x * p;
}

__global__ void __launch_bounds__(256) scanout_kernel(float4* __restrict__ out)
{
    const unsigned OUT4 = (unsigned)T_STEPS * BATCH * (HID / 4); // 4,194,304
    const unsigned HB4  = (unsigned)BATCH * (HID / 4);           // 16,384

    int b   = blockIdx.x;        // batch element
    int tid = threadIdx.x;

    __shared__ float sH[2][8];
    __shared__ float sC;

    // chain-local parameters (only thread 0 really uses them)
    float ws_f = g_par[0][0], A2_f = g_par[0][2], R2_f = g_par[0][3];
    float ws_i = g_par[1][0], A2_i = g_par[1][2], R2_i = g_par[1][3];
    float ws_g = g_par[2][0], A_g  = g_par[2][4], R_g  = g_par[2][5];
    float ws_o = g_par[3][0], A2_o = g_par[3][2], R2_o = g_par[3][3];
    float off_f = g_par[0][1], off_i = g_par[1][1], off_g = g_par[2][1], off_o = g_par[3][1];

    float H = 0.f, C = 0.f;
    const float4* Xd = g_xdot;

#define LOADADJ(t) \
    ({ float4 v_ = Xd[(t) * BATCH + b]; \
       v_.x += off_f; v_.y += off_i; v_.z += off_g; v_.w += off_o; v_; })

    float4 q[8];
    if (tid == 0) {
#pragma unroll
        for (int j = 0; j < 8; j++) q[j] = LOADADJ(j);
    }

#define STEP(xd, kk, jj)                                              \
    {                                                                 \
        float cf = __cosf(fmaf(H, ws_f, (xd).x));                     \
        float ci = __cosf(fmaf(H, ws_i, (xd).y));                     \
        float cg = __cosf(fmaf(H, ws_g, (xd).z));                     \
        float co = __cosf(fmaf(H, ws_o, (xd).w));                     \
        float fv = fmaf(ptanh_half(fmaf(R2_f, cf, A2_f)), 0.5f, 0.5f);\
        float iv = fmaf(ptanh_half(fmaf(R2_i, ci, A2_i)), 0.5f, 0.5f);\
        float gv = htanh(fmaf(R_g, cg, A_g));                         \
        float ov = fmaf(ptanh_half(fmaf(R2_o, co, A2_o)), 0.5f, 0.5f);\
        C = fmaf(fv, C, iv * gv);                                     \
        H = ov * htanh(C);                                            \
        sH[(kk) & 1][jj] = H;                                         \
    }

    // 32 compute chunks + 1 drain iteration; writers trail compute by one chunk
#pragma unroll 1
    for (int k = 0; k <= 32; k++) {
        if (tid == 0) {
            if (k < 32) {
                int t0 = k * 8;
#pragma unroll
                for (int j = 0; j < 8; j++) {
                    float4 cur = q[j];
                    if (t0 + 8 + j < T_STEPS) q[j] = LOADADJ(t0 + 8 + j);
                    STEP(cur, k, j);
                }
            } else {
                sC = C;
            }
        }
        if (tid >= 32 && k >= 1) {
            int c = k - 1;                       // chunk being written
            const float* hs = sH[c & 1];
            unsigned rowbase = (unsigned)c * 8u; // first t of chunk
#pragma unroll 1
            for (int u = tid - 32; u < 1024; u += 224) {
                int tl  = u >> 7;                // 0..7
                int pos = u & 127;               // float4 within the 512-wide row
                float v = hs[tl];
                unsigned idx = ((rowbase + tl) * BATCH + (unsigned)b) * (HID / 4) + pos;
                __stcs(out + idx, make_float4(v, v, v, v));
            }
        }
        __syncthreads();
    }
#undef STEP
#undef LOADADJ

    // tail: hx (= H at t=255, in sH[1][7]) and cx (= sC)
    float hfin = sH[1][7];
    float cfin = sC;
    if (tid < 128) {
        unsigned idx = OUT4 + (unsigned)b * (HID / 4) + tid;
        __stcs(out + idx, make_float4(hfin, hfin, hfin, hfin));
    } else {
        unsigned idx = OUT4 + HB4 + (unsigned)b * (HID / 4) + (tid - 128);
        __stcs(out + idx, make_float4(cfin, cfin, cfin, cfin));
    }
}

// ---------------- launch ----------------
extern "C" void kernel_launch(void* const* d_in, const int* in_sizes, int n_in,
                              void* d_out, int out_size)
{
    const float* X  = (const float*)d_in[0];
    const float* Wf = (const float*)d_in[1];
    const float* bf = (const float*)d_in[2];
    const float* Pf = (const float*)d_in[3];
    const float* Wi = (const float*)d_in[4];
    const float* bi = (const float*)d_in[5];
    const float* Pi = (const float*)d_in[6];
    const float* Wg = (const float*)d_in[7];
    const float* bg = (const float*)d_in[8];
    const float* Pg = (const float*)d_in[9];
    const float* Wo = (const float*)d_in[10];
    const float* bo = (const float*)d_in[11];
    const float* Po = (const float*)d_in[12];

    // blocks 0-3: circuits; blocks 4..2051: xdot (32768 rows / 16 rows per block)
    prep_kernel<<<4 + (T_STEPS * BATCH) / 16, 256>>>(
        X, Wf, Wi, Wg, Wo, bf, bi, bg, bo, Pf, Pi, Pg, Po);

    // one block per batch element; scan + output streaming fused
    scanout_kernel<<<BATCH, 256>>>((float4*)d_out);
}